// round 3
// baseline (speedup 1.0000x reference)
#include <cuda_runtime.h>
#include <cuda_bf16.h>

#define NN 100000
#define EE 800000
#define DD 64
#define HH 4
#define HC 256

// ---- scratch (static device globals: allocation-free) ----
__device__ float g_q[(size_t)NN * HC];                 // fp32 Q  [N][256]
__device__ __nv_bfloat16 g_kv[(size_t)NN * 512];       // bf16 K||V per node: [N][512]
__device__ float g_skip[(size_t)NN * DD];
__device__ float g_h[(size_t)NN * DD];
__device__ int   g_cnt[NN];
__device__ int   g_indptr[NN + 1];
__device__ int   g_cursor[NN];
__device__ int   g_col[EE];

// ================= CSR build (per call, deterministic input) =================
__global__ void zero_cnt_kernel() {
    int i = blockIdx.x * blockDim.x + threadIdx.x;
    if (i < NN) g_cnt[i] = 0;
}

__global__ void hist_kernel(const int* __restrict__ ei) {
    int e = blockIdx.x * blockDim.x + threadIdx.x;
    if (e < EE) atomicAdd(&g_cnt[ei[EE + e]], 1);
}

// single-block exclusive scan over g_cnt -> g_indptr / g_cursor
__global__ void __launch_bounds__(1024) scan_kernel() {
    __shared__ int s_w[32];
    __shared__ int s_carry;
    int tid = threadIdx.x, lane = tid & 31, wid = tid >> 5;
    if (tid == 0) s_carry = 0;
    __syncthreads();
    const int CH = (NN + 1 + 1023) / 1024;
    for (int c = 0; c < CH; c++) {
        int i = c * 1024 + tid;
        int v = (i < NN) ? g_cnt[i] : 0;
        int x = v;
#pragma unroll
        for (int d = 1; d < 32; d <<= 1) {
            int t = __shfl_up_sync(0xffffffffu, x, d);
            if (lane >= d) x += t;
        }
        if (lane == 31) s_w[wid] = x;
        __syncthreads();
        int carry = s_carry;
        if (wid == 0) {
            int y = s_w[lane];
#pragma unroll
            for (int d = 1; d < 32; d <<= 1) {
                int t = __shfl_up_sync(0xffffffffu, y, d);
                if (lane >= d) y += t;
            }
            s_w[lane] = y;
        }
        __syncthreads();
        int offs = carry + (wid > 0 ? s_w[wid - 1] : 0);
        int excl = offs + x - v;
        if (i <= NN) {
            g_indptr[i] = excl;
            if (i < NN) g_cursor[i] = excl;
        }
        __syncthreads();
        if (tid == 0) s_carry = carry + s_w[31];
        __syncthreads();
    }
}

__global__ void scatter_kernel(const int* __restrict__ ei) {
    int e = blockIdx.x * blockDim.x + threadIdx.x;
    if (e < EE) {
        int d = ei[EE + e];
        int pos = atomicAdd(&g_cursor[d], 1);
        g_col[pos] = ei[e];
    }
}

// ===== fused QKV + skip GEMM, FFMA2 core =====
// X[nrows,64] @ {Wq,Wk,Wv(64x256), Ws(64x64)}
// grid: (ceil(nrows/64), 13). blockIdx.y: 0-3 q(fp32), 4-7 k(bf16), 8-11 v(bf16), 12 skip(fp32)
#define FMA2(d, a, b) asm("fma.rn.f32x2 %0, %1, %2, %0;" : "+l"(d) : "l"(a), "l"(b))

__global__ void __launch_bounds__(256) gemm_kernel(
    const float* __restrict__ Xext, int useGh,
    const float* __restrict__ Wq, const float* __restrict__ bq,
    const float* __restrict__ Wk, const float* __restrict__ bk,
    const float* __restrict__ Wv, const float* __restrict__ bv,
    const float* __restrict__ Ws, const float* __restrict__ bs,
    int nrows)
{
    const float* X = useGh ? g_h : Xext;
    __shared__ float2 Xs2[64][64];   // [k][row] value duplicated into both halves
    __shared__ float2 Wt2[64][32];   // [k][col pair]

    int bc = blockIdx.y;
    int row0 = blockIdx.x * 64;
    const float* W; const float* bias; int ld; int col0; int mode; // 0=q,1=k,2=v,3=skip
    if (bc < 4)       { W = Wq; bias = bq; ld = 256; col0 = bc * 64;       mode = 0; }
    else if (bc < 8)  { W = Wk; bias = bk; ld = 256; col0 = (bc - 4) * 64; mode = 1; }
    else if (bc < 12) { W = Wv; bias = bv; ld = 256; col0 = (bc - 8) * 64; mode = 2; }
    else              { W = Ws; bias = bs; ld = 64;  col0 = 0;             mode = 3; }

    int tid = threadIdx.x;
#pragma unroll
    for (int j = 0; j < 4; j++) {
        int idx = tid + j * 256;     // 0..1023 float4 slots
        int r   = idx >> 4;          // 0..63
        int c4  = idx & 15;          // 0..15
        int gr  = row0 + r;
        float4 xv = make_float4(0.f, 0.f, 0.f, 0.f);
        if (gr < nrows)
            xv = *reinterpret_cast<const float4*>(X + (size_t)gr * 64 + c4 * 4);
        Xs2[c4 * 4 + 0][r] = make_float2(xv.x, xv.x);
        Xs2[c4 * 4 + 1][r] = make_float2(xv.y, xv.y);
        Xs2[c4 * 4 + 2][r] = make_float2(xv.z, xv.z);
        Xs2[c4 * 4 + 3][r] = make_float2(xv.w, xv.w);
        float4 wv = *reinterpret_cast<const float4*>(W + (size_t)r * ld + col0 + c4 * 4);
        Wt2[r][c4 * 2 + 0] = make_float2(wv.x, wv.y);
        Wt2[r][c4 * 2 + 1] = make_float2(wv.z, wv.w);
    }
    __syncthreads();

    int tx = tid & 15, ty = tid >> 4;
    unsigned long long acc[4][2] = {};   // each holds a packed float2 (init 0.0f pair)

#pragma unroll
    for (int kk = 0; kk < 64; kk++) {
        ulonglong2 aa01 = *reinterpret_cast<const ulonglong2*>(&Xs2[kk][ty * 4]);
        ulonglong2 aa23 = *reinterpret_cast<const ulonglong2*>(&Xs2[kk][ty * 4 + 2]);
        ulonglong2 bb   = *reinterpret_cast<const ulonglong2*>(&Wt2[kk][tx * 2]);
        FMA2(acc[0][0], aa01.x, bb.x); FMA2(acc[0][1], aa01.x, bb.y);
        FMA2(acc[1][0], aa01.y, bb.x); FMA2(acc[1][1], aa01.y, bb.y);
        FMA2(acc[2][0], aa23.x, bb.x); FMA2(acc[2][1], aa23.x, bb.y);
        FMA2(acc[3][0], aa23.y, bb.x); FMA2(acc[3][1], aa23.y, bb.y);
    }

    float4 bb4 = *reinterpret_cast<const float4*>(bias + col0 + tx * 4);
#pragma unroll
    for (int i = 0; i < 4; i++) {
        int gr = row0 + ty * 4 + i;
        if (gr >= nrows) continue;
        float2 p0 = *reinterpret_cast<float2*>(&acc[i][0]);
        float2 p1 = *reinterpret_cast<float2*>(&acc[i][1]);
        float4 o;
        o.x = p0.x + bb4.x; o.y = p0.y + bb4.y;
        o.z = p1.x + bb4.z; o.w = p1.y + bb4.w;
        if (mode == 0) {
            *reinterpret_cast<float4*>(g_q + (size_t)gr * 256 + col0 + tx * 4) = o;
        } else if (mode == 3) {
            *reinterpret_cast<float4*>(g_skip + (size_t)gr * 64 + tx * 4) = o;
        } else {
            __nv_bfloat162 h0 = __floats2bfloat162_rn(o.x, o.y);
            __nv_bfloat162 h1 = __floats2bfloat162_rn(o.z, o.w);
            uint2 u;
            u.x = *reinterpret_cast<unsigned*>(&h0);
            u.y = *reinterpret_cast<unsigned*>(&h1);
            size_t base = (size_t)gr * 512 + (mode == 2 ? 256 : 0) + col0 + tx * 4;
            *reinterpret_cast<uint2*>(g_kv + base) = u;
        }
    }
}

// ====== fused attention + epilogue: one warp per destination node ======
__device__ __forceinline__ float2 bf2f(unsigned u) {
    __nv_bfloat162 t = *reinterpret_cast<__nv_bfloat162*>(&u);
    return __bfloat1622float2(t);
}

__global__ void __launch_bounds__(256) attn_kernel(float* __restrict__ out_ext,
                                                   int to_gh, int relu) {
    int n = (blockIdx.x * blockDim.x + threadIdx.x) >> 5;
    if (n >= NN) return;
    int lane = threadIdx.x & 31;
    int h = lane >> 3, m = lane & 7;

    size_t qbase = (size_t)n * HC + h * 64 + m * 8;
    float4 q0 = *reinterpret_cast<const float4*>(g_q + qbase);
    float4 q1 = *reinterpret_cast<const float4*>(g_q + qbase + 4);

    float acc[8] = {0.f, 0.f, 0.f, 0.f, 0.f, 0.f, 0.f, 0.f};
    float den = 0.f;

    const uint4* kvp = reinterpret_cast<const uint4*>(g_kv);  // 8 bf16 per uint4; node stride 64
    int koff = h * 8 + m;

    int e0 = g_indptr[n], e1 = g_indptr[n + 1];
    int s = (e0 < e1) ? g_col[e0] : 0;
    for (int e = e0; e < e1; e++) {
        int snext = (e + 1 < e1) ? g_col[e + 1] : 0;
        uint4 kr = kvp[(size_t)s * 64 + koff];
        uint4 vr = kvp[(size_t)s * 64 + 32 + koff];

        float2 k0 = bf2f(kr.x), k1 = bf2f(kr.y), k2 = bf2f(kr.z), k3 = bf2f(kr.w);
        float p = q0.x * k0.x + q0.y * k0.y + q0.z * k1.x + q0.w * k1.y
                + q1.x * k2.x + q1.y * k2.y + q1.z * k3.x + q1.w * k3.y;
        p += __shfl_xor_sync(0xffffffffu, p, 1);
        p += __shfl_xor_sync(0xffffffffu, p, 2);
        p += __shfl_xor_sync(0xffffffffu, p, 4);
        float ex = __expf(p * 0.125f);   // 1/sqrt(64)

        float2 v0 = bf2f(vr.x), v1 = bf2f(vr.y), v2 = bf2f(vr.z), v3 = bf2f(vr.w);
        acc[0] += ex * v0.x; acc[1] += ex * v0.y;
        acc[2] += ex * v1.x; acc[3] += ex * v1.y;
        acc[4] += ex * v2.x; acc[5] += ex * v2.y;
        acc[6] += ex * v3.x; acc[7] += ex * v3.y;
        den += ex;
        s = snext;
    }

    float inv = 1.0f / (den + 1e-16f);
#pragma unroll
    for (int j = 0; j < 8; j++) {
        float r = acc[j] * inv;
        r += __shfl_xor_sync(0xffffffffu, r, 8);
        r += __shfl_xor_sync(0xffffffffu, r, 16);
        acc[j] = r * 0.25f;
    }

    if (h == 0) {   // lanes 0..7 write channels m*8..m*8+7
        float* out = to_gh ? g_h : out_ext;
        size_t ob = (size_t)n * DD + m * 8;
        float4 s0 = *reinterpret_cast<const float4*>(g_skip + ob);
        float4 s1 = *reinterpret_cast<const float4*>(g_skip + ob + 4);
        float4 o0, o1;
        o0.x = acc[0] + s0.x; o0.y = acc[1] + s0.y;
        o0.z = acc[2] + s0.z; o0.w = acc[3] + s0.w;
        o1.x = acc[4] + s1.x; o1.y = acc[5] + s1.y;
        o1.z = acc[6] + s1.z; o1.w = acc[7] + s1.w;
        if (relu) {
            o0.x = fmaxf(o0.x, 0.f); o0.y = fmaxf(o0.y, 0.f);
            o0.z = fmaxf(o0.z, 0.f); o0.w = fmaxf(o0.w, 0.f);
            o1.x = fmaxf(o1.x, 0.f); o1.y = fmaxf(o1.y, 0.f);
            o1.z = fmaxf(o1.z, 0.f); o1.w = fmaxf(o1.w, 0.f);
        }
        *reinterpret_cast<float4*>(out + ob)     = o0;
        *reinterpret_cast<float4*>(out + ob + 4) = o1;
    }
}

extern "C" void kernel_launch(void* const* d_in, const int* in_sizes, int n_in,
                              void* d_out, int out_size) {
    const float* x   = (const float*)d_in[0];
    const int*   ei  = (const int*)d_in[1];
    const float* Wq1 = (const float*)d_in[2];
    const float* bq1 = (const float*)d_in[3];
    const float* Wk1 = (const float*)d_in[4];
    const float* bk1 = (const float*)d_in[5];
    const float* Wv1 = (const float*)d_in[6];
    const float* bv1 = (const float*)d_in[7];
    const float* Ws1 = (const float*)d_in[8];
    const float* bs1 = (const float*)d_in[9];
    const float* Wq2 = (const float*)d_in[10];
    const float* bq2 = (const float*)d_in[11];
    const float* Wk2 = (const float*)d_in[12];
    const float* bk2 = (const float*)d_in[13];
    const float* Wv2 = (const float*)d_in[14];
    const float* bv2 = (const float*)d_in[15];
    const float* Ws2 = (const float*)d_in[16];
    const float* bs2 = (const float*)d_in[17];
    float* out = (float*)d_out;

    // ---- CSR by destination (rebuilt every call; graph-capturable) ----
    zero_cnt_kernel<<<(NN + 255) / 256, 256>>>();
    hist_kernel<<<(EE + 255) / 256, 256>>>(ei);
    scan_kernel<<<1, 1024>>>();
    scatter_kernel<<<(EE + 255) / 256, 256>>>(ei);

    dim3 ggrid((NN + 63) / 64, 13);
    int attn_blocks = (NN * 32 + 255) / 256;   // one warp per node

    // ---- layer 1 ----
    gemm_kernel<<<ggrid, 256>>>(x, 0, Wq1, bq1, Wk1, bk1, Wv1, bv1, Ws1, bs1, NN);
    attn_kernel<<<attn_blocks, 256>>>(nullptr, /*to_gh=*/1, /*relu=*/1);

    // ---- layer 2 ----
    gemm_kernel<<<ggrid, 256>>>(nullptr, 1, Wq2, bq2, Wk2, bk2, Wv2, bv2, Ws2, bs2, NN);
    attn_kernel<<<attn_blocks, 256>>>(out, /*to_gh=*/0, /*relu=*/0);
}

// round 4
// speedup vs baseline: 1.8592x; 1.8592x over previous
#include <cuda_runtime.h>
#include <cuda_bf16.h>

#define NN 100000
#define EE 800000
#define DD 64
#define HH 4
#define HC 256

// ---- scratch (static device globals: allocation-free) ----
__device__ float g_q[(size_t)NN * HC];                 // fp32 Q  [N][256]
__device__ __nv_bfloat16 g_kv[(size_t)NN * 512];       // bf16 K||V per node: [N][512]
__device__ float g_skip[(size_t)NN * DD];
__device__ float g_h[(size_t)NN * DD];
__device__ int   g_cnt[NN];
__device__ int   g_indptr[NN + 1];
__device__ int   g_cursor[NN];
__device__ int   g_col[EE];

// ================= CSR build (per call, deterministic input) =================
__global__ void zero_cnt_kernel() {
    int i = blockIdx.x * blockDim.x + threadIdx.x;
    if (i < NN) g_cnt[i] = 0;
}

__global__ void hist_kernel(const int* __restrict__ ei) {
    int e = blockIdx.x * blockDim.x + threadIdx.x;
    if (e < EE) atomicAdd(&g_cnt[ei[EE + e]], 1);
}

// single-block exclusive scan over g_cnt -> g_indptr / g_cursor
__global__ void __launch_bounds__(1024) scan_kernel() {
    __shared__ int s_w[32];
    __shared__ int s_carry;
    int tid = threadIdx.x, lane = tid & 31, wid = tid >> 5;
    if (tid == 0) s_carry = 0;
    __syncthreads();
    const int CH = (NN + 1 + 1023) / 1024;
    for (int c = 0; c < CH; c++) {
        int i = c * 1024 + tid;
        int v = (i < NN) ? g_cnt[i] : 0;
        int x = v;
#pragma unroll
        for (int d = 1; d < 32; d <<= 1) {
            int t = __shfl_up_sync(0xffffffffu, x, d);
            if (lane >= d) x += t;
        }
        if (lane == 31) s_w[wid] = x;
        __syncthreads();
        int carry = s_carry;
        if (wid == 0) {
            int y = s_w[lane];
#pragma unroll
            for (int d = 1; d < 32; d <<= 1) {
                int t = __shfl_up_sync(0xffffffffu, y, d);
                if (lane >= d) y += t;
            }
            s_w[lane] = y;
        }
        __syncthreads();
        int offs = carry + (wid > 0 ? s_w[wid - 1] : 0);
        int excl = offs + x - v;
        if (i <= NN) {
            g_indptr[i] = excl;
            if (i < NN) g_cursor[i] = excl;
        }
        __syncthreads();
        if (tid == 0) s_carry = carry + s_w[31];
        __syncthreads();
    }
}

__global__ void scatter_kernel(const int* __restrict__ ei) {
    int e = blockIdx.x * blockDim.x + threadIdx.x;
    if (e < EE) {
        int d = ei[EE + e];
        int pos = atomicAdd(&g_cursor[d], 1);
        g_col[pos] = ei[e];
    }
}

// ===== fused QKV + skip GEMM, FFMA2 core, 128x64 tile, 8x8 per thread =====
// grid: (ceil(nrows/128), 13). blockIdx.y: 0-3 q(fp32), 4-7 k(bf16), 8-11 v(bf16), 12 skip(fp32)
#define FMA2(d, a, b) asm("fma.rn.f32x2 %0, %1, %2, %0;" : "+l"(d) : "l"(a), "l"(b))

#define XS_LD 66   // stride for Xs rows (conflict-free scalar broadcast)
#define WT_LD 68   // stride for Wt rows (16B-aligned float4)

__global__ void __launch_bounds__(128) gemm_kernel(
    const float* __restrict__ Xext, int useGh,
    const float* __restrict__ Wq, const float* __restrict__ bq,
    const float* __restrict__ Wk, const float* __restrict__ bk,
    const float* __restrict__ Wv, const float* __restrict__ bv,
    const float* __restrict__ Ws, const float* __restrict__ bs,
    int nrows)
{
    const float* X = useGh ? g_h : Xext;
    __shared__ float Xs[128 * XS_LD];   // [row][k], row-major
    __shared__ float Wt[64 * WT_LD];    // [k][col]

    int bc = blockIdx.y;
    int row0 = blockIdx.x * 128;
    const float* W; const float* bias; int ld; int col0; int mode; // 0=q,1=k,2=v,3=skip
    if (bc < 4)       { W = Wq; bias = bq; ld = 256; col0 = bc * 64;       mode = 0; }
    else if (bc < 8)  { W = Wk; bias = bk; ld = 256; col0 = (bc - 4) * 64; mode = 1; }
    else if (bc < 12) { W = Wv; bias = bv; ld = 256; col0 = (bc - 8) * 64; mode = 2; }
    else              { W = Ws; bias = bs; ld = 64;  col0 = 0;             mode = 3; }

    int tid = threadIdx.x;
    // load X tile: 128 rows x 64 cols = 2048 float4 slots, 16 per thread
#pragma unroll
    for (int j = 0; j < 16; j++) {
        int idx = tid + j * 128;
        int r = idx >> 4, c4 = idx & 15;
        int gr = row0 + r;
        float4 xv = make_float4(0.f, 0.f, 0.f, 0.f);
        if (gr < nrows)
            xv = *reinterpret_cast<const float4*>(X + (size_t)gr * 64 + c4 * 4);
        *reinterpret_cast<float2*>(&Xs[r * XS_LD + c4 * 4])     = make_float2(xv.x, xv.y);
        *reinterpret_cast<float2*>(&Xs[r * XS_LD + c4 * 4 + 2]) = make_float2(xv.z, xv.w);
    }
    // load W tile: 64 rows x 64 cols = 1024 float4 slots, 8 per thread
#pragma unroll
    for (int j = 0; j < 8; j++) {
        int idx = tid + j * 128;
        int r = idx >> 4, c4 = idx & 15;
        float4 wv = *reinterpret_cast<const float4*>(W + (size_t)r * ld + col0 + c4 * 4);
        *reinterpret_cast<float4*>(&Wt[r * WT_LD + c4 * 4]) = wv;
    }
    __syncthreads();

    int tx = tid >> 4;    // 0..7  col group (8 cols)
    int ty = tid & 15;    // 0..15 row group (rows ty + 16*i)

    unsigned long long acc[8][4] = {};   // packed f32x2 accumulators

#pragma unroll 16
    for (int kk = 0; kk < 64; kk++) {
        unsigned long long ad[8];
#pragma unroll
        for (int i = 0; i < 8; i++) {
            unsigned ab = __float_as_uint(Xs[(ty + 16 * i) * XS_LD + kk]);
            asm("mov.b64 %0, {%1, %1};" : "=l"(ad[i]) : "r"(ab));
        }
        float4 b0 = *reinterpret_cast<const float4*>(&Wt[kk * WT_LD + tx * 8]);
        float4 b1 = *reinterpret_cast<const float4*>(&Wt[kk * WT_LD + tx * 8 + 4]);
        ulonglong2 bbA = *reinterpret_cast<ulonglong2*>(&b0);
        ulonglong2 bbB = *reinterpret_cast<ulonglong2*>(&b1);
#pragma unroll
        for (int i = 0; i < 8; i++) {
            FMA2(acc[i][0], ad[i], bbA.x);
            FMA2(acc[i][1], ad[i], bbA.y);
            FMA2(acc[i][2], ad[i], bbB.x);
            FMA2(acc[i][3], ad[i], bbB.y);
        }
    }

    float4 bb0 = *reinterpret_cast<const float4*>(bias + col0 + tx * 8);
    float4 bb1 = *reinterpret_cast<const float4*>(bias + col0 + tx * 8 + 4);
#pragma unroll
    for (int i = 0; i < 8; i++) {
        int gr = row0 + ty + 16 * i;
        if (gr >= nrows) continue;
        float2 p0 = *reinterpret_cast<float2*>(&acc[i][0]);
        float2 p1 = *reinterpret_cast<float2*>(&acc[i][1]);
        float2 p2 = *reinterpret_cast<float2*>(&acc[i][2]);
        float2 p3 = *reinterpret_cast<float2*>(&acc[i][3]);
        float4 o0, o1;
        o0.x = p0.x + bb0.x; o0.y = p0.y + bb0.y;
        o0.z = p1.x + bb0.z; o0.w = p1.y + bb0.w;
        o1.x = p2.x + bb1.x; o1.y = p2.y + bb1.y;
        o1.z = p3.x + bb1.z; o1.w = p3.y + bb1.w;
        if (mode == 0) {
            float* dst = g_q + (size_t)gr * 256 + col0 + tx * 8;
            *reinterpret_cast<float4*>(dst)     = o0;
            *reinterpret_cast<float4*>(dst + 4) = o1;
        } else if (mode == 3) {
            float* dst = g_skip + (size_t)gr * 64 + tx * 8;
            *reinterpret_cast<float4*>(dst)     = o0;
            *reinterpret_cast<float4*>(dst + 4) = o1;
        } else {
            __nv_bfloat162 h0 = __floats2bfloat162_rn(o0.x, o0.y);
            __nv_bfloat162 h1 = __floats2bfloat162_rn(o0.z, o0.w);
            __nv_bfloat162 h2 = __floats2bfloat162_rn(o1.x, o1.y);
            __nv_bfloat162 h3 = __floats2bfloat162_rn(o1.z, o1.w);
            uint4 u;
            u.x = *reinterpret_cast<unsigned*>(&h0);
            u.y = *reinterpret_cast<unsigned*>(&h1);
            u.z = *reinterpret_cast<unsigned*>(&h2);
            u.w = *reinterpret_cast<unsigned*>(&h3);
            size_t base = (size_t)gr * 512 + (mode == 2 ? 256 : 0) + col0 + tx * 8;
            *reinterpret_cast<uint4*>(g_kv + base) = u;
        }
    }
}

// ====== fused attention + epilogue: one warp per destination node ======
__device__ __forceinline__ float2 bf2f(unsigned u) {
    __nv_bfloat162 t = *reinterpret_cast<__nv_bfloat162*>(&u);
    return __bfloat1622float2(t);
}

__global__ void __launch_bounds__(256) attn_kernel(float* __restrict__ out_ext,
                                                   int to_gh, int relu) {
    int n = (blockIdx.x * blockDim.x + threadIdx.x) >> 5;
    if (n >= NN) return;
    int lane = threadIdx.x & 31;
    int h = lane >> 3, m = lane & 7;

    size_t qbase = (size_t)n * HC + h * 64 + m * 8;
    float4 q0 = *reinterpret_cast<const float4*>(g_q + qbase);
    float4 q1 = *reinterpret_cast<const float4*>(g_q + qbase + 4);

    float acc[8] = {0.f, 0.f, 0.f, 0.f, 0.f, 0.f, 0.f, 0.f};
    float den = 0.f;

    const uint4* kvp = reinterpret_cast<const uint4*>(g_kv);  // 8 bf16 per uint4; node stride 64
    int koff = h * 8 + m;

    int e0 = g_indptr[n], e1 = g_indptr[n + 1];
    int s = (e0 < e1) ? g_col[e0] : 0;
    for (int e = e0; e < e1; e++) {
        int snext = (e + 1 < e1) ? g_col[e + 1] : 0;
        uint4 kr = kvp[(size_t)s * 64 + koff];
        uint4 vr = kvp[(size_t)s * 64 + 32 + koff];

        float2 k0 = bf2f(kr.x), k1 = bf2f(kr.y), k2 = bf2f(kr.z), k3 = bf2f(kr.w);
        float p = q0.x * k0.x + q0.y * k0.y + q0.z * k1.x + q0.w * k1.y
                + q1.x * k2.x + q1.y * k2.y + q1.z * k3.x + q1.w * k3.y;
        p += __shfl_xor_sync(0xffffffffu, p, 1);
        p += __shfl_xor_sync(0xffffffffu, p, 2);
        p += __shfl_xor_sync(0xffffffffu, p, 4);
        float ex = __expf(p * 0.125f);   // 1/sqrt(64)

        float2 v0 = bf2f(vr.x), v1 = bf2f(vr.y), v2 = bf2f(vr.z), v3 = bf2f(vr.w);
        acc[0] += ex * v0.x; acc[1] += ex * v0.y;
        acc[2] += ex * v1.x; acc[3] += ex * v1.y;
        acc[4] += ex * v2.x; acc[5] += ex * v2.y;
        acc[6] += ex * v3.x; acc[7] += ex * v3.y;
        den += ex;
        s = snext;
    }

    float inv = 1.0f / (den + 1e-16f);
#pragma unroll
    for (int j = 0; j < 8; j++) {
        float r = acc[j] * inv;
        r += __shfl_xor_sync(0xffffffffu, r, 8);
        r += __shfl_xor_sync(0xffffffffu, r, 16);
        acc[j] = r * 0.25f;
    }

    if (h == 0) {   // lanes 0..7 write channels m*8..m*8+7
        float* out = to_gh ? g_h : out_ext;
        size_t ob = (size_t)n * DD + m * 8;
        float4 s0 = *reinterpret_cast<const float4*>(g_skip + ob);
        float4 s1 = *reinterpret_cast<const float4*>(g_skip + ob + 4);
        float4 o0, o1;
        o0.x = acc[0] + s0.x; o0.y = acc[1] + s0.y;
        o0.z = acc[2] + s0.z; o0.w = acc[3] + s0.w;
        o1.x = acc[4] + s1.x; o1.y = acc[5] + s1.y;
        o1.z = acc[6] + s1.z; o1.w = acc[7] + s1.w;
        if (relu) {
            o0.x = fmaxf(o0.x, 0.f); o0.y = fmaxf(o0.y, 0.f);
            o0.z = fmaxf(o0.z, 0.f); o0.w = fmaxf(o0.w, 0.f);
            o1.x = fmaxf(o1.x, 0.f); o1.y = fmaxf(o1.y, 0.f);
            o1.z = fmaxf(o1.z, 0.f); o1.w = fmaxf(o1.w, 0.f);
        }
        *reinterpret_cast<float4*>(out + ob)     = o0;
        *reinterpret_cast<float4*>(out + ob + 4) = o1;
    }
}

extern "C" void kernel_launch(void* const* d_in, const int* in_sizes, int n_in,
                              void* d_out, int out_size) {
    const float* x   = (const float*)d_in[0];
    const int*   ei  = (const int*)d_in[1];
    const float* Wq1 = (const float*)d_in[2];
    const float* bq1 = (const float*)d_in[3];
    const float* Wk1 = (const float*)d_in[4];
    const float* bk1 = (const float*)d_in[5];
    const float* Wv1 = (const float*)d_in[6];
    const float* bv1 = (const float*)d_in[7];
    const float* Ws1 = (const float*)d_in[8];
    const float* bs1 = (const float*)d_in[9];
    const float* Wq2 = (const float*)d_in[10];
    const float* bq2 = (const float*)d_in[11];
    const float* Wk2 = (const float*)d_in[12];
    const float* bk2 = (const float*)d_in[13];
    const float* Wv2 = (const float*)d_in[14];
    const float* bv2 = (const float*)d_in[15];
    const float* Ws2 = (const float*)d_in[16];
    const float* bs2 = (const float*)d_in[17];
    float* out = (float*)d_out;

    // ---- CSR by destination (rebuilt every call; graph-capturable) ----
    zero_cnt_kernel<<<(NN + 255) / 256, 256>>>();
    hist_kernel<<<(EE + 255) / 256, 256>>>(ei);
    scan_kernel<<<1, 1024>>>();
    scatter_kernel<<<(EE + 255) / 256, 256>>>(ei);

    dim3 ggrid((NN + 127) / 128, 13);
    int attn_blocks = (NN * 32 + 255) / 256;   // one warp per node

    // ---- layer 1 ----
    gemm_kernel<<<ggrid, 128>>>(x, 0, Wq1, bq1, Wk1, bk1, Wv1, bv1, Ws1, bs1, NN);
    attn_kernel<<<attn_blocks, 256>>>(nullptr, /*to_gh=*/1, /*relu=*/1);

    // ---- layer 2 ----
    gemm_kernel<<<ggrid, 128>>>(nullptr, 1, Wq2, bq2, Wk2, bk2, Wv2, bv2, Ws2, bs2, NN);
    attn_kernel<<<attn_blocks, 256>>>(out, /*to_gh=*/0, /*relu=*/0);
}

// round 6
// speedup vs baseline: 2.0212x; 1.0871x over previous
#include <cuda_runtime.h>
#include <cuda_bf16.h>
#include <cstdint>

#define NN 100000
#define EE 800000
#define DD 64
#define HH 4
#define HC 256

// ---- scratch (static device globals: allocation-free) ----
__device__ float g_q[(size_t)NN * HC];                 // fp32 Q  [N][256]
__device__ __nv_bfloat16 g_kv[(size_t)NN * 512];       // bf16 K||V per node: [N][512]
__device__ float g_skip[(size_t)NN * DD];
__device__ float g_h[(size_t)NN * DD];
__device__ int   g_cnt[NN];
__device__ int   g_indptr[NN + 1];
__device__ int   g_cursor[NN];
__device__ int   g_col[EE];
// W in bf16 hi/lo, transposed: [layer][chunk 13][part 2][n 64][k 64]
__device__ __nv_bfloat16 g_wb[2 * 13 * 2 * 64 * 64];

__device__ __forceinline__ uint32_t smem_u32(const void* p) {
    uint32_t a;
    asm("{ .reg .u64 t; cvta.to.shared.u64 t, %1; cvt.u32.u64 %0, t; }" : "=r"(a) : "l"(p));
    return a;
}

#define LDMX4(d0, d1, d2, d3, a) \
    asm volatile("ldmatrix.sync.aligned.m8n8.x4.shared.b16 {%0,%1,%2,%3}, [%4];" \
                 : "=r"(d0), "=r"(d1), "=r"(d2), "=r"(d3) : "r"(a))

#define MMA16816(c, a, b0, b1) \
    asm volatile("mma.sync.aligned.m16n8k16.row.col.f32.bf16.bf16.f32 " \
                 "{%0,%1,%2,%3}, {%4,%5,%6,%7}, {%8,%9}, {%0,%1,%2,%3};" \
                 : "+f"((c)[0]), "+f"((c)[1]), "+f"((c)[2]), "+f"((c)[3]) \
                 : "r"((a)[0]), "r"((a)[1]), "r"((a)[2]), "r"((a)[3]), "r"(b0), "r"(b1))

// ================= CSR build (per call, deterministic input) =================
__global__ void zero_cnt_kernel() {
    int i = blockIdx.x * blockDim.x + threadIdx.x;
    if (i < NN) g_cnt[i] = 0;
}
__global__ void hist_kernel(const int* __restrict__ ei) {
    int e = blockIdx.x * blockDim.x + threadIdx.x;
    if (e < EE) atomicAdd(&g_cnt[ei[EE + e]], 1);
}
__global__ void __launch_bounds__(1024) scan_kernel() {
    __shared__ int s_w[32];
    __shared__ int s_carry;
    int tid = threadIdx.x, lane = tid & 31, wid = tid >> 5;
    if (tid == 0) s_carry = 0;
    __syncthreads();
    const int CH = (NN + 1 + 1023) / 1024;
    for (int c = 0; c < CH; c++) {
        int i = c * 1024 + tid;
        int v = (i < NN) ? g_cnt[i] : 0;
        int x = v;
#pragma unroll
        for (int d = 1; d < 32; d <<= 1) {
            int t = __shfl_up_sync(0xffffffffu, x, d);
            if (lane >= d) x += t;
        }
        if (lane == 31) s_w[wid] = x;
        __syncthreads();
        int carry = s_carry;
        if (wid == 0) {
            int y = s_w[lane];
#pragma unroll
            for (int d = 1; d < 32; d <<= 1) {
                int t = __shfl_up_sync(0xffffffffu, y, d);
                if (lane >= d) y += t;
            }
            s_w[lane] = y;
        }
        __syncthreads();
        int offs = carry + (wid > 0 ? s_w[wid - 1] : 0);
        int excl = offs + x - v;
        if (i <= NN) {
            g_indptr[i] = excl;
            if (i < NN) g_cursor[i] = excl;
        }
        __syncthreads();
        if (tid == 0) s_carry = carry + s_w[31];
        __syncthreads();
    }
}
__global__ void scatter_kernel(const int* __restrict__ ei) {
    int e = blockIdx.x * blockDim.x + threadIdx.x;
    if (e < EE) {
        int d = ei[EE + e];
        int pos = atomicAdd(&g_cursor[d], 1);
        g_col[pos] = ei[e];
    }
}

// ============ W prep: transpose + bf16 hi/lo split into g_wb ============
__global__ void prep_w(const float* __restrict__ Wq, const float* __restrict__ Wk,
                       const float* __restrict__ Wv, const float* __restrict__ Ws,
                       __nv_bfloat16* __restrict__ dst) {
    int c = blockIdx.x;   // 0..12
    for (int i = threadIdx.x; i < 4096; i += 256) {
        int n = i >> 6, k = i & 63;
        float w;
        if (c < 4)       w = Wq[k * 256 + c * 64 + n];
        else if (c < 8)  w = Wk[k * 256 + (c - 4) * 64 + n];
        else if (c < 12) w = Wv[k * 256 + (c - 8) * 64 + n];
        else             w = Ws[k * 64 + n];
        __nv_bfloat16 hi = __float2bfloat16(w);
        float lo = w - __bfloat162float(hi);
        dst[c * 8192 + i]        = hi;
        dst[c * 8192 + 4096 + i] = __float2bfloat16(lo);
    }
}

// ============ mma.sync GEMM: 128 rows x 832 cols, bf16x3 split ============
// dyn smem layout (bytes):
#define SM_BIAS 0                    // 832 floats = 3328
#define SM_AHI  3584                 // 128 x 72 bf16 = 18432
#define SM_ALO  22016                // 18432
#define SM_BHI  40448                // 64 x 72 bf16 = 9216
#define SM_BLO  49664                // 9216
#define SM_STG  58880                // 128 x 68 fp32 = 34816
#define SM_TOT  93696
#define LDA 72
#define LDB 72
#define STG 68

__global__ void __launch_bounds__(128) tc_gemm(
    const float* __restrict__ Xext, int useGh,
    const float* __restrict__ bq, const float* __restrict__ bk,
    const float* __restrict__ bv, const float* __restrict__ bs,
    const __nv_bfloat16* __restrict__ wb, int nrows)
{
    extern __shared__ char smem[];
    uint32_t sb = smem_u32(smem);
    const float* X = useGh ? g_h : Xext;
    int tid = threadIdx.x, w = tid >> 5, l = tid & 31;
    int row0 = blockIdx.x * 128;
    float* biasSm = reinterpret_cast<float*>(smem + SM_BIAS);
    float* stage  = reinterpret_cast<float*>(smem + SM_STG);

    // bias staging: [13][64]
    for (int i = tid; i < 832; i += 128) {
        int c = i >> 6, j = i & 63;
        float b;
        if (c < 4)       b = bq[i];
        else if (c < 8)  b = bk[i - 256];
        else if (c < 12) b = bv[i - 512];
        else             b = bs[j];
        biasSm[i] = b;
    }

    // A load + bf16 hi/lo split into smem [128][LDA]
#pragma unroll
    for (int j = 0; j < 16; j++) {
        int idx = tid + j * 128;
        int r = idx >> 4, c4 = idx & 15;
        int gr = row0 + r;
        float4 xv = make_float4(0.f, 0.f, 0.f, 0.f);
        if (gr < nrows)
            xv = *reinterpret_cast<const float4*>(X + (size_t)gr * 64 + c4 * 4);
        __nv_bfloat16 h0 = __float2bfloat16(xv.x);
        __nv_bfloat16 h1 = __float2bfloat16(xv.y);
        __nv_bfloat16 h2 = __float2bfloat16(xv.z);
        __nv_bfloat16 h3 = __float2bfloat16(xv.w);
        __nv_bfloat162 hh0; hh0.x = h0; hh0.y = h1;
        __nv_bfloat162 hh1; hh1.x = h2; hh1.y = h3;
        __nv_bfloat162 ll0 = __floats2bfloat162_rn(xv.x - __bfloat162float(h0),
                                                   xv.y - __bfloat162float(h1));
        __nv_bfloat162 ll1 = __floats2bfloat162_rn(xv.z - __bfloat162float(h2),
                                                   xv.w - __bfloat162float(h3));
        uint2 uh, ul;
        uh.x = *reinterpret_cast<unsigned*>(&hh0);
        uh.y = *reinterpret_cast<unsigned*>(&hh1);
        ul.x = *reinterpret_cast<unsigned*>(&ll0);
        ul.y = *reinterpret_cast<unsigned*>(&ll1);
        size_t boff = (size_t)(r * LDA + c4 * 4) * 2;
        *reinterpret_cast<uint2*>(smem + SM_AHI + boff) = uh;
        *reinterpret_cast<uint2*>(smem + SM_ALO + boff) = ul;
    }

    // lane-fixed fragment address components
    int arow = w * 32 + (l & 15);
    int acol = (l >> 4) * 8;
    int bn   = (l & 7) + ((l >> 4) << 3);
    int bk8  = (l & 8);

    for (int c = 0; c < 13; c++) {
        // ---- load B chunk (hi+lo) into smem [64][LDB] ----
        for (int i = tid; i < 1024; i += 128) {
            int part = i >> 9, j = i & 511;
            int n = j >> 3, k8 = j & 7;
            uint4 v = reinterpret_cast<const uint4*>(wb + (size_t)c * 8192 + part * 4096)[j];
            char* p = smem + (part ? SM_BLO : SM_BHI) + n * (LDB * 2) + k8 * 16;
            *reinterpret_cast<uint2*>(p)     = make_uint2(v.x, v.y);
            *reinterpret_cast<uint2*>(p + 8) = make_uint2(v.z, v.w);
        }
        __syncthreads();

        float acc[2][8][4];
#pragma unroll
        for (int mt = 0; mt < 2; mt++)
#pragma unroll
            for (int nt = 0; nt < 8; nt++)
#pragma unroll
                for (int q = 0; q < 4; q++) acc[mt][nt][q] = 0.f;

#pragma unroll
        for (int kt = 0; kt < 4; kt++) {
            uint32_t ah[2][4], al[2][4];
#pragma unroll
            for (int mt = 0; mt < 2; mt++) {
                uint32_t off = (uint32_t)(((arow + mt * 16) * LDA + kt * 16 + acol) * 2);
                LDMX4(ah[mt][0], ah[mt][1], ah[mt][2], ah[mt][3], sb + SM_AHI + off);
                LDMX4(al[mt][0], al[mt][1], al[mt][2], al[mt][3], sb + SM_ALO + off);
            }
            uint32_t bh[4][4], bl[4][4];
#pragma unroll
            for (int np = 0; np < 4; np++) {
                uint32_t off = (uint32_t)(((bn + np * 16) * LDB + kt * 16 + bk8) * 2);
                LDMX4(bh[np][0], bh[np][1], bh[np][2], bh[np][3], sb + SM_BHI + off);
                LDMX4(bl[np][0], bl[np][1], bl[np][2], bl[np][3], sb + SM_BLO + off);
            }
#pragma unroll
            for (int mt = 0; mt < 2; mt++) {
#pragma unroll
                for (int np = 0; np < 4; np++) {
                    MMA16816(acc[mt][np * 2],     ah[mt], bh[np][0], bh[np][1]);
                    MMA16816(acc[mt][np * 2],     ah[mt], bl[np][0], bl[np][1]);
                    MMA16816(acc[mt][np * 2],     al[mt], bh[np][0], bh[np][1]);
                    MMA16816(acc[mt][np * 2 + 1], ah[mt], bh[np][2], bh[np][3]);
                    MMA16816(acc[mt][np * 2 + 1], ah[mt], bl[np][2], bl[np][3]);
                    MMA16816(acc[mt][np * 2 + 1], al[mt], bh[np][2], bh[np][3]);
                }
            }
        }

        // ---- stage accumulators to smem ----
        int rs = w * 32 + (l >> 2);
        int cs = (l & 3) * 2;
#pragma unroll
        for (int mt = 0; mt < 2; mt++) {
#pragma unroll
            for (int nt = 0; nt < 8; nt++) {
                int col = nt * 8 + cs;
                *reinterpret_cast<float2*>(stage + (rs + mt * 16) * STG + col) =
                    make_float2(acc[mt][nt][0], acc[mt][nt][1]);
                *reinterpret_cast<float2*>(stage + (rs + mt * 16 + 8) * STG + col) =
                    make_float2(acc[mt][nt][2], acc[mt][nt][3]);
            }
        }
        __syncthreads();

        // ---- coalesced typed store ----
#pragma unroll
        for (int j = 0; j < 16; j++) {
            int idx = tid + j * 128;
            int r = idx >> 4, c4 = idx & 15;
            int gr = row0 + r;
            if (gr >= nrows) continue;
            float4 o = *reinterpret_cast<const float4*>(stage + r * STG + c4 * 4);
            const float4 bb = *reinterpret_cast<const float4*>(biasSm + c * 64 + c4 * 4);
            o.x += bb.x; o.y += bb.y; o.z += bb.z; o.w += bb.w;
            if (c < 4) {
                *reinterpret_cast<float4*>(g_q + (size_t)gr * 256 + c * 64 + c4 * 4) = o;
            } else if (c < 12) {
                int col0 = (c < 8) ? (c - 4) * 64 : (c - 8) * 64 + 256;
                __nv_bfloat162 p0 = __floats2bfloat162_rn(o.x, o.y);
                __nv_bfloat162 p1 = __floats2bfloat162_rn(o.z, o.w);
                uint2 u;
                u.x = *reinterpret_cast<unsigned*>(&p0);
                u.y = *reinterpret_cast<unsigned*>(&p1);
                *reinterpret_cast<uint2*>(g_kv + (size_t)gr * 512 + col0 + c4 * 4) = u;
            } else {
                *reinterpret_cast<float4*>(g_skip + (size_t)gr * 64 + c4 * 4) = o;
            }
        }
        __syncthreads();
    }
}

// ====== fused attention + epilogue: one warp per destination node ======
__device__ __forceinline__ float2 bf2f(unsigned u) {
    __nv_bfloat162 t = *reinterpret_cast<__nv_bfloat162*>(&u);
    return __bfloat1622float2(t);
}

__global__ void __launch_bounds__(256) attn_kernel(float* __restrict__ out_ext,
                                                   int to_gh, int relu) {
    int n = (blockIdx.x * blockDim.x + threadIdx.x) >> 5;
    if (n >= NN) return;
    int lane = threadIdx.x & 31;
    int h = lane >> 3, m = lane & 7;

    size_t qbase = (size_t)n * HC + h * 64 + m * 8;
    float4 q0 = *reinterpret_cast<const float4*>(g_q + qbase);
    float4 q1 = *reinterpret_cast<const float4*>(g_q + qbase + 4);

    float acc[8] = {0.f, 0.f, 0.f, 0.f, 0.f, 0.f, 0.f, 0.f};
    float den = 0.f;

    const uint4* kvp = reinterpret_cast<const uint4*>(g_kv);  // node stride 64 uint4
    int koff = h * 8 + m;

    int e0 = g_indptr[n], e1 = g_indptr[n + 1];
    if (e0 < e1) {
        int s = g_col[e0];
        uint4 kr = kvp[(size_t)s * 64 + koff];
        uint4 vr = kvp[(size_t)s * 64 + 32 + koff];
        for (int e = e0; e < e1; e++) {
            int sn = (e + 1 < e1) ? g_col[e + 1] : s;
            uint4 krn = kvp[(size_t)sn * 64 + koff];
            uint4 vrn = kvp[(size_t)sn * 64 + 32 + koff];

            float2 k0 = bf2f(kr.x), k1 = bf2f(kr.y), k2 = bf2f(kr.z), k3 = bf2f(kr.w);
            float p = q0.x * k0.x + q0.y * k0.y + q0.z * k1.x + q0.w * k1.y
                    + q1.x * k2.x + q1.y * k2.y + q1.z * k3.x + q1.w * k3.y;
            p += __shfl_xor_sync(0xffffffffu, p, 1);
            p += __shfl_xor_sync(0xffffffffu, p, 2);
            p += __shfl_xor_sync(0xffffffffu, p, 4);
            float ex = __expf(p * 0.125f);   // 1/sqrt(64)

            float2 v0 = bf2f(vr.x), v1 = bf2f(vr.y), v2 = bf2f(vr.z), v3 = bf2f(vr.w);
            acc[0] += ex * v0.x; acc[1] += ex * v0.y;
            acc[2] += ex * v1.x; acc[3] += ex * v1.y;
            acc[4] += ex * v2.x; acc[5] += ex * v2.y;
            acc[6] += ex * v3.x; acc[7] += ex * v3.y;
            den += ex;
            kr = krn; vr = vrn;
        }
    }

    float inv = 1.0f / (den + 1e-16f);
#pragma unroll
    for (int j = 0; j < 8; j++) {
        float r = acc[j] * inv;
        r += __shfl_xor_sync(0xffffffffu, r, 8);
        r += __shfl_xor_sync(0xffffffffu, r, 16);
        acc[j] = r * 0.25f;
    }

    if (h == 0) {
        float* out = to_gh ? g_h : out_ext;
        size_t ob = (size_t)n * DD + m * 8;
        float4 s0 = *reinterpret_cast<const float4*>(g_skip + ob);
        float4 s1 = *reinterpret_cast<const float4*>(g_skip + ob + 4);
        float4 o0, o1;
        o0.x = acc[0] + s0.x; o0.y = acc[1] + s0.y;
        o0.z = acc[2] + s0.z; o0.w = acc[3] + s0.w;
        o1.x = acc[4] + s1.x; o1.y = acc[5] + s1.y;
        o1.z = acc[6] + s1.z; o1.w = acc[7] + s1.w;
        if (relu) {
            o0.x = fmaxf(o0.x, 0.f); o0.y = fmaxf(o0.y, 0.f);
            o0.z = fmaxf(o0.z, 0.f); o0.w = fmaxf(o0.w, 0.f);
            o1.x = fmaxf(o1.x, 0.f); o1.y = fmaxf(o1.y, 0.f);
            o1.z = fmaxf(o1.z, 0.f); o1.w = fmaxf(o1.w, 0.f);
        }
        *reinterpret_cast<float4*>(out + ob)     = o0;
        *reinterpret_cast<float4*>(out + ob + 4) = o1;
    }
}

extern "C" void kernel_launch(void* const* d_in, const int* in_sizes, int n_in,
                              void* d_out, int out_size) {
    const float* x   = (const float*)d_in[0];
    const int*   ei  = (const int*)d_in[1];
    const float* Wq1 = (const float*)d_in[2];
    const float* bq1 = (const float*)d_in[3];
    const float* Wk1 = (const float*)d_in[4];
    const float* bk1 = (const float*)d_in[5];
    const float* Wv1 = (const float*)d_in[6];
    const float* bv1 = (const float*)d_in[7];
    const float* Ws1 = (const float*)d_in[8];
    const float* bs1 = (const float*)d_in[9];
    const float* Wq2 = (const float*)d_in[10];
    const float* bq2 = (const float*)d_in[11];
    const float* Wk2 = (const float*)d_in[12];
    const float* bk2 = (const float*)d_in[13];
    const float* Wv2 = (const float*)d_in[14];
    const float* bv2 = (const float*)d_in[15];
    const float* Ws2 = (const float*)d_in[16];
    const float* bs2 = (const float*)d_in[17];
    float* out = (float*)d_out;

    cudaFuncSetAttribute(tc_gemm, cudaFuncAttributeMaxDynamicSharedMemorySize, SM_TOT);

    __nv_bfloat16* wb_dev = nullptr;
    cudaGetSymbolAddress((void**)&wb_dev, g_wb);

    // ---- CSR by destination ----
    zero_cnt_kernel<<<(NN + 255) / 256, 256>>>();
    hist_kernel<<<(EE + 255) / 256, 256>>>(ei);
    scan_kernel<<<1, 1024>>>();
    scatter_kernel<<<(EE + 255) / 256, 256>>>(ei);

    // ---- W prep (both layers) ----
    prep_w<<<13, 256>>>(Wq1, Wk1, Wv1, Ws1, wb_dev);
    prep_w<<<13, 256>>>(Wq2, Wk2, Wv2, Ws2, wb_dev + 13 * 8192);

    int gemm_blocks = (NN + 127) / 128;
    int attn_blocks = (NN * 32 + 255) / 256;

    // ---- layer 1 ----
    tc_gemm<<<gemm_blocks, 128, SM_TOT>>>(x, 0, bq1, bk1, bv1, bs1, wb_dev, NN);
    attn_kernel<<<attn_blocks, 256>>>(nullptr, /*to_gh=*/1, /*relu=*/1);

    // ---- layer 2 ----
    tc_gemm<<<gemm_blocks, 128, SM_TOT>>>(nullptr, 1, bq2, bk2, bv2, bs2, wb_dev + 13 * 8192, NN);
    attn_kernel<<<attn_blocks, 256>>>(out, /*to_gh=*/0, /*relu=*/0);
}

// round 7
// speedup vs baseline: 2.5761x; 1.2745x over previous
#include <cuda_runtime.h>
#include <cuda_bf16.h>
#include <cstdint>

#define NN 100000
#define EE 800000
#define DD 64
#define HH 4
#define HC 256

// ---- scratch (static device globals: allocation-free) ----
__device__ float g_q[(size_t)NN * HC];                 // fp32 Q  [N][256]
__device__ __nv_bfloat16 g_kv[(size_t)NN * 512];       // bf16 K||V per node: [N][512]
__device__ float g_skip[(size_t)NN * DD];
__device__ float g_h[(size_t)NN * DD];
__device__ int   g_cnt[NN];
__device__ int   g_indptr[NN + 1];
__device__ int   g_cursor[NN];
__device__ int   g_col[EE];
// W in bf16 hi/lo, transposed: [layer][chunk 13][part 2][n 64][k 64]
__device__ __nv_bfloat16 g_wb[2 * 13 * 2 * 64 * 64];

__device__ __forceinline__ uint32_t smem_u32(const void* p) {
    uint32_t a;
    asm("{ .reg .u64 t; cvta.to.shared.u64 t, %1; cvt.u32.u64 %0, t; }" : "=r"(a) : "l"(p));
    return a;
}

#define LDMX4(d0, d1, d2, d3, a) \
    asm volatile("ldmatrix.sync.aligned.m8n8.x4.shared.b16 {%0,%1,%2,%3}, [%4];" \
                 : "=r"(d0), "=r"(d1), "=r"(d2), "=r"(d3) : "r"(a))

#define MMA16816(c, a, b0, b1) \
    asm volatile("mma.sync.aligned.m16n8k16.row.col.f32.bf16.bf16.f32 " \
                 "{%0,%1,%2,%3}, {%4,%5,%6,%7}, {%8,%9}, {%0,%1,%2,%3};" \
                 : "+f"((c)[0]), "+f"((c)[1]), "+f"((c)[2]), "+f"((c)[3]) \
                 : "r"((a)[0]), "r"((a)[1]), "r"((a)[2]), "r"((a)[3]), "r"(b0), "r"(b1))

// ================= CSR build (per call, deterministic input) =================
__global__ void zero_cnt_kernel() {
    int i = blockIdx.x * blockDim.x + threadIdx.x;
    if (i < NN) g_cnt[i] = 0;
}
__global__ void hist_kernel(const int* __restrict__ ei) {
    int e = blockIdx.x * blockDim.x + threadIdx.x;
    if (e < EE) atomicAdd(&g_cnt[ei[EE + e]], 1);
}
__global__ void __launch_bounds__(1024) scan_kernel() {
    __shared__ int s_w[32];
    __shared__ int s_carry;
    int tid = threadIdx.x, lane = tid & 31, wid = tid >> 5;
    if (tid == 0) s_carry = 0;
    __syncthreads();
    const int CH = (NN + 1 + 1023) / 1024;
    for (int c = 0; c < CH; c++) {
        int i = c * 1024 + tid;
        int v = (i < NN) ? g_cnt[i] : 0;
        int x = v;
#pragma unroll
        for (int d = 1; d < 32; d <<= 1) {
            int t = __shfl_up_sync(0xffffffffu, x, d);
            if (lane >= d) x += t;
        }
        if (lane == 31) s_w[wid] = x;
        __syncthreads();
        int carry = s_carry;
        if (wid == 0) {
            int y = s_w[lane];
#pragma unroll
            for (int d = 1; d < 32; d <<= 1) {
                int t = __shfl_up_sync(0xffffffffu, y, d);
                if (lane >= d) y += t;
            }
            s_w[lane] = y;
        }
        __syncthreads();
        int offs = carry + (wid > 0 ? s_w[wid - 1] : 0);
        int excl = offs + x - v;
        if (i <= NN) {
            g_indptr[i] = excl;
            if (i < NN) g_cursor[i] = excl;
        }
        __syncthreads();
        if (tid == 0) s_carry = carry + s_w[31];
        __syncthreads();
    }
}
__global__ void scatter_kernel(const int* __restrict__ ei) {
    int e = blockIdx.x * blockDim.x + threadIdx.x;
    if (e < EE) {
        int d = ei[EE + e];
        int pos = atomicAdd(&g_cursor[d], 1);
        g_col[pos] = ei[e];
    }
}

// ============ W prep: transpose + bf16 hi/lo split into g_wb (both layers) ============
__global__ void prep_w(const float* __restrict__ Wq1, const float* __restrict__ Wk1,
                       const float* __restrict__ Wv1, const float* __restrict__ Ws1,
                       const float* __restrict__ Wq2, const float* __restrict__ Wk2,
                       const float* __restrict__ Wv2, const float* __restrict__ Ws2,
                       __nv_bfloat16* __restrict__ dst0) {
    int b = blockIdx.x;           // 0..25
    int layer = b / 13, c = b % 13;
    const float* Wq = layer ? Wq2 : Wq1;
    const float* Wk = layer ? Wk2 : Wk1;
    const float* Wv = layer ? Wv2 : Wv1;
    const float* Ws = layer ? Ws2 : Ws1;
    __nv_bfloat16* dst = dst0 + (size_t)layer * 13 * 8192;
    for (int i = threadIdx.x; i < 4096; i += 256) {
        int n = i >> 6, k = i & 63;
        float w;
        if (c < 4)       w = Wq[k * 256 + c * 64 + n];
        else if (c < 8)  w = Wk[k * 256 + (c - 4) * 64 + n];
        else if (c < 12) w = Wv[k * 256 + (c - 8) * 64 + n];
        else             w = Ws[k * 64 + n];
        __nv_bfloat16 hi = __float2bfloat16(w);
        float lo = w - __bfloat162float(hi);
        dst[c * 8192 + i]        = hi;
        dst[c * 8192 + 4096 + i] = __float2bfloat16(lo);
    }
}

// ============ mma.sync GEMM: 128 rows x 832 cols, bf16x3 split ============
#define SM_BIAS 0                    // 832 floats = 3328
#define SM_AHI  3584                 // 128 x 72 bf16 = 18432
#define SM_ALO  22016                // 18432
#define SM_BHI  40448                // 64 x 72 bf16 = 9216
#define SM_BLO  49664                // 9216
#define SM_STG  58880                // 128 x 68 fp32 = 34816
#define SM_TOT  93696
#define LDA 72
#define LDB 72
#define STG 68

__global__ void __launch_bounds__(128) tc_gemm(
    const float* __restrict__ Xext, int useGh,
    const float* __restrict__ bq, const float* __restrict__ bk,
    const float* __restrict__ bv, const float* __restrict__ bs,
    const __nv_bfloat16* __restrict__ wb, int nrows)
{
    extern __shared__ char smem[];
    uint32_t sb = smem_u32(smem);
    const float* X = useGh ? g_h : Xext;
    int tid = threadIdx.x, w = tid >> 5, l = tid & 31;
    int row0 = blockIdx.x * 128;
    float* biasSm = reinterpret_cast<float*>(smem + SM_BIAS);
    float* stage  = reinterpret_cast<float*>(smem + SM_STG);

    // bias staging: [13][64]
    for (int i = tid; i < 832; i += 128) {
        int c = i >> 6, j = i & 63;
        float b;
        if (c < 4)       b = bq[i];
        else if (c < 8)  b = bk[i - 256];
        else if (c < 12) b = bv[i - 512];
        else             b = bs[j];
        biasSm[i] = b;
    }

    // A load + bf16 hi/lo split into smem [128][LDA]
#pragma unroll
    for (int j = 0; j < 16; j++) {
        int idx = tid + j * 128;
        int r = idx >> 4, c4 = idx & 15;
        int gr = row0 + r;
        float4 xv = make_float4(0.f, 0.f, 0.f, 0.f);
        if (gr < nrows)
            xv = *reinterpret_cast<const float4*>(X + (size_t)gr * 64 + c4 * 4);
        __nv_bfloat16 h0 = __float2bfloat16(xv.x);
        __nv_bfloat16 h1 = __float2bfloat16(xv.y);
        __nv_bfloat16 h2 = __float2bfloat16(xv.z);
        __nv_bfloat16 h3 = __float2bfloat16(xv.w);
        __nv_bfloat162 hh0; hh0.x = h0; hh0.y = h1;
        __nv_bfloat162 hh1; hh1.x = h2; hh1.y = h3;
        __nv_bfloat162 ll0 = __floats2bfloat162_rn(xv.x - __bfloat162float(h0),
                                                   xv.y - __bfloat162float(h1));
        __nv_bfloat162 ll1 = __floats2bfloat162_rn(xv.z - __bfloat162float(h2),
                                                   xv.w - __bfloat162float(h3));
        uint2 uh, ul;
        uh.x = *reinterpret_cast<unsigned*>(&hh0);
        uh.y = *reinterpret_cast<unsigned*>(&hh1);
        ul.x = *reinterpret_cast<unsigned*>(&ll0);
        ul.y = *reinterpret_cast<unsigned*>(&ll1);
        size_t boff = (size_t)(r * LDA + c4 * 4) * 2;
        *reinterpret_cast<uint2*>(smem + SM_AHI + boff) = uh;
        *reinterpret_cast<uint2*>(smem + SM_ALO + boff) = ul;
    }

    // lane-fixed fragment address components
    int arow = w * 32 + (l & 15);
    int acol = (l >> 4) * 8;
    int bn   = (l & 7) + ((l >> 4) << 3);
    int bk8  = (l & 8);

    // ---- register prefetch of B chunk 0 (8 x uint4 per thread = 16KB) ----
    uint4 pre[8];
#pragma unroll
    for (int j = 0; j < 8; j++)
        pre[j] = reinterpret_cast<const uint4*>(wb)[tid + j * 128];

    for (int c = 0; c < 13; c++) {
        // ---- publish prefetched B chunk into smem [64][LDB] (hi then lo) ----
#pragma unroll
        for (int j = 0; j < 8; j++) {
            int i = tid + j * 128;
            int part = i >> 9, jj = i & 511;
            int n = jj >> 3, k8 = jj & 7;
            char* p = smem + (part ? SM_BLO : SM_BHI) + n * (LDB * 2) + k8 * 16;
            *reinterpret_cast<uint2*>(p)     = make_uint2(pre[j].x, pre[j].y);
            *reinterpret_cast<uint2*>(p + 8) = make_uint2(pre[j].z, pre[j].w);
        }
        __syncthreads();

        // ---- issue LDGs for next chunk (overlap with MMA) ----
        if (c + 1 < 13) {
#pragma unroll
            for (int j = 0; j < 8; j++)
                pre[j] = reinterpret_cast<const uint4*>(wb + (size_t)(c + 1) * 8192)[tid + j * 128];
        }

        float acc[2][8][4];
#pragma unroll
        for (int mt = 0; mt < 2; mt++)
#pragma unroll
            for (int nt = 0; nt < 8; nt++)
#pragma unroll
                for (int q = 0; q < 4; q++) acc[mt][nt][q] = 0.f;

#pragma unroll
        for (int kt = 0; kt < 4; kt++) {
            uint32_t ah[2][4], al[2][4];
#pragma unroll
            for (int mt = 0; mt < 2; mt++) {
                uint32_t off = (uint32_t)(((arow + mt * 16) * LDA + kt * 16 + acol) * 2);
                LDMX4(ah[mt][0], ah[mt][1], ah[mt][2], ah[mt][3], sb + SM_AHI + off);
                LDMX4(al[mt][0], al[mt][1], al[mt][2], al[mt][3], sb + SM_ALO + off);
            }
            uint32_t bh[4][4], bl[4][4];
#pragma unroll
            for (int np = 0; np < 4; np++) {
                uint32_t off = (uint32_t)(((bn + np * 16) * LDB + kt * 16 + bk8) * 2);
                LDMX4(bh[np][0], bh[np][1], bh[np][2], bh[np][3], sb + SM_BHI + off);
                LDMX4(bl[np][0], bl[np][1], bl[np][2], bl[np][3], sb + SM_BLO + off);
            }
#pragma unroll
            for (int mt = 0; mt < 2; mt++) {
#pragma unroll
                for (int np = 0; np < 4; np++) {
                    MMA16816(acc[mt][np * 2],     ah[mt], bh[np][0], bh[np][1]);
                    MMA16816(acc[mt][np * 2],     ah[mt], bl[np][0], bl[np][1]);
                    MMA16816(acc[mt][np * 2],     al[mt], bh[np][0], bh[np][1]);
                    MMA16816(acc[mt][np * 2 + 1], ah[mt], bh[np][2], bh[np][3]);
                    MMA16816(acc[mt][np * 2 + 1], ah[mt], bl[np][2], bl[np][3]);
                    MMA16816(acc[mt][np * 2 + 1], al[mt], bh[np][2], bh[np][3]);
                }
            }
        }

        // ---- stage accumulators to smem ----
        int rs = w * 32 + (l >> 2);
        int cs = (l & 3) * 2;
#pragma unroll
        for (int mt = 0; mt < 2; mt++) {
#pragma unroll
            for (int nt = 0; nt < 8; nt++) {
                int col = nt * 8 + cs;
                *reinterpret_cast<float2*>(stage + (rs + mt * 16) * STG + col) =
                    make_float2(acc[mt][nt][0], acc[mt][nt][1]);
                *reinterpret_cast<float2*>(stage + (rs + mt * 16 + 8) * STG + col) =
                    make_float2(acc[mt][nt][2], acc[mt][nt][3]);
            }
        }
        __syncthreads();

        // ---- coalesced typed store ----
#pragma unroll
        for (int j = 0; j < 16; j++) {
            int idx = tid + j * 128;
            int r = idx >> 4, c4 = idx & 15;
            int gr = row0 + r;
            if (gr >= nrows) continue;
            float4 o = *reinterpret_cast<const float4*>(stage + r * STG + c4 * 4);
            const float4 bb = *reinterpret_cast<const float4*>(biasSm + c * 64 + c4 * 4);
            o.x += bb.x; o.y += bb.y; o.z += bb.z; o.w += bb.w;
            if (c < 4) {
                *reinterpret_cast<float4*>(g_q + (size_t)gr * 256 + c * 64 + c4 * 4) = o;
            } else if (c < 12) {
                int col0 = (c < 8) ? (c - 4) * 64 : (c - 8) * 64 + 256;
                __nv_bfloat162 p0 = __floats2bfloat162_rn(o.x, o.y);
                __nv_bfloat162 p1 = __floats2bfloat162_rn(o.z, o.w);
                uint2 u;
                u.x = *reinterpret_cast<unsigned*>(&p0);
                u.y = *reinterpret_cast<unsigned*>(&p1);
                *reinterpret_cast<uint2*>(g_kv + (size_t)gr * 512 + col0 + c4 * 4) = u;
            } else {
                *reinterpret_cast<float4*>(g_skip + (size_t)gr * 64 + c4 * 4) = o;
            }
        }
        __syncthreads();
    }
}

// ====== fused attention + epilogue: one warp per destination node ======
__device__ __forceinline__ float2 bf2f(unsigned u) {
    __nv_bfloat162 t = *reinterpret_cast<__nv_bfloat162*>(&u);
    return __bfloat1622float2(t);
}

__global__ void __launch_bounds__(256) attn_kernel(float* __restrict__ out_ext,
                                                   int to_gh, int relu) {
    int n = (blockIdx.x * blockDim.x + threadIdx.x) >> 5;
    if (n >= NN) return;
    int lane = threadIdx.x & 31;
    int h = lane >> 3, m = lane & 7;

    size_t qbase = (size_t)n * HC + h * 64 + m * 8;
    float4 q0 = *reinterpret_cast<const float4*>(g_q + qbase);
    float4 q1 = *reinterpret_cast<const float4*>(g_q + qbase + 4);

    float acc[8] = {0.f, 0.f, 0.f, 0.f, 0.f, 0.f, 0.f, 0.f};
    float den = 0.f;

    const uint4* kvp = reinterpret_cast<const uint4*>(g_kv);  // node stride 64 uint4
    int koff = h * 8 + m;

    int e0 = g_indptr[n], e1 = g_indptr[n + 1];
    int e = e0;

    // ---- 2-edge unrolled main loop (dual ILP chains) ----
    for (; e + 2 <= e1; e += 2) {
        int sA = g_col[e], sB = g_col[e + 1];
        uint4 krA = kvp[(size_t)sA * 64 + koff];
        uint4 krB = kvp[(size_t)sB * 64 + koff];
        uint4 vrA = kvp[(size_t)sA * 64 + 32 + koff];
        uint4 vrB = kvp[(size_t)sB * 64 + 32 + koff];

        float2 a0 = bf2f(krA.x), a1 = bf2f(krA.y), a2 = bf2f(krA.z), a3 = bf2f(krA.w);
        float2 c0 = bf2f(krB.x), c1 = bf2f(krB.y), c2 = bf2f(krB.z), c3 = bf2f(krB.w);
        float pA = q0.x * a0.x + q0.y * a0.y + q0.z * a1.x + q0.w * a1.y
                 + q1.x * a2.x + q1.y * a2.y + q1.z * a3.x + q1.w * a3.y;
        float pB = q0.x * c0.x + q0.y * c0.y + q0.z * c1.x + q0.w * c1.y
                 + q1.x * c2.x + q1.y * c2.y + q1.z * c3.x + q1.w * c3.y;
        pA += __shfl_xor_sync(0xffffffffu, pA, 1);
        pB += __shfl_xor_sync(0xffffffffu, pB, 1);
        pA += __shfl_xor_sync(0xffffffffu, pA, 2);
        pB += __shfl_xor_sync(0xffffffffu, pB, 2);
        pA += __shfl_xor_sync(0xffffffffu, pA, 4);
        pB += __shfl_xor_sync(0xffffffffu, pB, 4);
        float exA = __expf(pA * 0.125f);
        float exB = __expf(pB * 0.125f);

        float2 vA0 = bf2f(vrA.x), vA1 = bf2f(vrA.y), vA2 = bf2f(vrA.z), vA3 = bf2f(vrA.w);
        float2 vB0 = bf2f(vrB.x), vB1 = bf2f(vrB.y), vB2 = bf2f(vrB.z), vB3 = bf2f(vrB.w);
        acc[0] += exA * vA0.x + exB * vB0.x;
        acc[1] += exA * vA0.y + exB * vB0.y;
        acc[2] += exA * vA1.x + exB * vB1.x;
        acc[3] += exA * vA1.y + exB * vB1.y;
        acc[4] += exA * vA2.x + exB * vB2.x;
        acc[5] += exA * vA2.y + exB * vB2.y;
        acc[6] += exA * vA3.x + exB * vB3.x;
        acc[7] += exA * vA3.y + exB * vB3.y;
        den += exA + exB;
    }
    // ---- tail edge ----
    if (e < e1) {
        int s = g_col[e];
        uint4 kr = kvp[(size_t)s * 64 + koff];
        uint4 vr = kvp[(size_t)s * 64 + 32 + koff];
        float2 k0 = bf2f(kr.x), k1 = bf2f(kr.y), k2 = bf2f(kr.z), k3 = bf2f(kr.w);
        float p = q0.x * k0.x + q0.y * k0.y + q0.z * k1.x + q0.w * k1.y
                + q1.x * k2.x + q1.y * k2.y + q1.z * k3.x + q1.w * k3.y;
        p += __shfl_xor_sync(0xffffffffu, p, 1);
        p += __shfl_xor_sync(0xffffffffu, p, 2);
        p += __shfl_xor_sync(0xffffffffu, p, 4);
        float ex = __expf(p * 0.125f);
        float2 v0 = bf2f(vr.x), v1 = bf2f(vr.y), v2 = bf2f(vr.z), v3 = bf2f(vr.w);
        acc[0] += ex * v0.x; acc[1] += ex * v0.y;
        acc[2] += ex * v1.x; acc[3] += ex * v1.y;
        acc[4] += ex * v2.x; acc[5] += ex * v2.y;
        acc[6] += ex * v3.x; acc[7] += ex * v3.y;
        den += ex;
    }

    float inv = 1.0f / (den + 1e-16f);
#pragma unroll
    for (int j = 0; j < 8; j++) {
        float r = acc[j] * inv;
        r += __shfl_xor_sync(0xffffffffu, r, 8);
        r += __shfl_xor_sync(0xffffffffu, r, 16);
        acc[j] = r * 0.25f;
    }

    if (h == 0) {
        float* out = to_gh ? g_h : out_ext;
        size_t ob = (size_t)n * DD + m * 8;
        float4 s0 = *reinterpret_cast<const float4*>(g_skip + ob);
        float4 s1 = *reinterpret_cast<const float4*>(g_skip + ob + 4);
        float4 o0, o1;
        o0.x = acc[0] + s0.x; o0.y = acc[1] + s0.y;
        o0.z = acc[2] + s0.z; o0.w = acc[3] + s0.w;
        o1.x = acc[4] + s1.x; o1.y = acc[5] + s1.y;
        o1.z = acc[6] + s1.z; o1.w = acc[7] + s1.w;
        if (relu) {
            o0.x = fmaxf(o0.x, 0.f); o0.y = fmaxf(o0.y, 0.f);
            o0.z = fmaxf(o0.z, 0.f); o0.w = fmaxf(o0.w, 0.f);
            o1.x = fmaxf(o1.x, 0.f); o1.y = fmaxf(o1.y, 0.f);
            o1.z = fmaxf(o1.z, 0.f); o1.w = fmaxf(o1.w, 0.f);
        }
        *reinterpret_cast<float4*>(out + ob)     = o0;
        *reinterpret_cast<float4*>(out + ob + 4) = o1;
    }
}

extern "C" void kernel_launch(void* const* d_in, const int* in_sizes, int n_in,
                              void* d_out, int out_size) {
    const float* x   = (const float*)d_in[0];
    const int*   ei  = (const int*)d_in[1];
    const float* Wq1 = (const float*)d_in[2];
    const float* bq1 = (const float*)d_in[3];
    const float* Wk1 = (const float*)d_in[4];
    const float* bk1 = (const float*)d_in[5];
    const float* Wv1 = (const float*)d_in[6];
    const float* bv1 = (const float*)d_in[7];
    const float* Ws1 = (const float*)d_in[8];
    const float* bs1 = (const float*)d_in[9];
    const float* Wq2 = (const float*)d_in[10];
    const float* bq2 = (const float*)d_in[11];
    const float* Wk2 = (const float*)d_in[12];
    const float* bk2 = (const float*)d_in[13];
    const float* Wv2 = (const float*)d_in[14];
    const float* bv2 = (const float*)d_in[15];
    const float* Ws2 = (const float*)d_in[16];
    const float* bs2 = (const float*)d_in[17];
    float* out = (float*)d_out;

    cudaFuncSetAttribute(tc_gemm, cudaFuncAttributeMaxDynamicSharedMemorySize, SM_TOT);

    __nv_bfloat16* wb_dev = nullptr;
    cudaGetSymbolAddress((void**)&wb_dev, g_wb);

    // ---- CSR by destination ----
    zero_cnt_kernel<<<(NN + 255) / 256, 256>>>();
    hist_kernel<<<(EE + 255) / 256, 256>>>(ei);
    scan_kernel<<<1, 1024>>>();
    scatter_kernel<<<(EE + 255) / 256, 256>>>(ei);

    // ---- W prep (both layers, one launch) ----
    prep_w<<<26, 256>>>(Wq1, Wk1, Wv1, Ws1, Wq2, Wk2, Wv2, Ws2, wb_dev);

    int gemm_blocks = (NN + 127) / 128;
    int attn_blocks = (NN * 32 + 255) / 256;

    // ---- layer 1 ----
    tc_gemm<<<gemm_blocks, 128, SM_TOT>>>(x, 0, bq1, bk1, bv1, bs1, wb_dev, NN);
    attn_kernel<<<attn_blocks, 256>>>(nullptr, /*to_gh=*/1, /*relu=*/1);

    // ---- layer 2 ----
    tc_gemm<<<gemm_blocks, 128, SM_TOT>>>(nullptr, 1, bq2, bk2, bv2, bs2, wb_dev + 13 * 8192, NN);
    attn_kernel<<<attn_blocks, 256>>>(out, /*to_gh=*/0, /*relu=*/0);
}